// round 1
// baseline (speedup 1.0000x reference)
#include <cuda_runtime.h>
#include <math.h>

// Problem constants
#define Bb 8
#define Nn 4096
#define Cc 256
#define Hh 8
#define Dd 32
#define HID 1024
#define Mrows (Bb * Nn)           // 32768
#define ROWSZ ((size_t)Mrows * Cc) // 8388608

// ---------------- scratch (device globals; no allocations allowed) ---------
__device__ float g_xpos[ROWSZ];
__device__ float g_xln[ROWSZ];
__device__ float g_sln[ROWSZ];
__device__ float g_qkv[(size_t)Mrows * 3 * Cc];
__device__ float g_attnpre[ROWSZ];
__device__ float g_attnproj[ROWSZ];
__device__ float g_update[ROWSZ];
__device__ float g_hln[ROWSZ];
__device__ float g_fc1[(size_t)Mrows * HID];
__device__ float g_kv[Bb * Hh * Dd * Dd]; // 65536

// ---------------- helpers ---------------------------------------------------
__device__ __forceinline__ float2 block_sum2(float a, float b, float* sm) {
    // 256 threads = 8 warps. Returns (sum(a), sum(b)) to all threads.
    #pragma unroll
    for (int o = 16; o > 0; o >>= 1) {
        a += __shfl_down_sync(0xffffffffu, a, o);
        b += __shfl_down_sync(0xffffffffu, b, o);
    }
    int w = threadIdx.x >> 5, l = threadIdx.x & 31;
    if (l == 0) { sm[w] = a; sm[8 + w] = b; }
    __syncthreads();
    if (w == 0) {
        a = sm[l & 7]; b = sm[8 + (l & 7)];
        #pragma unroll
        for (int o = 4; o > 0; o >>= 1) {
            a += __shfl_down_sync(0xffffffffu, a, o);
            b += __shfl_down_sync(0xffffffffu, b, o);
        }
        if (l == 0) { sm[16] = a; sm[17] = b; }
    }
    __syncthreads();
    return make_float2(sm[16], sm[17]);
}

__device__ __forceinline__ float phi_fn(float x) {
    // elu(x)+1
    return x > 0.f ? x + 1.f : expf(x);
}

// ---------------- kernel 1: x_pos, LN1(x_pos), LN2(prev_state) -------------
__global__ void __launch_bounds__(256) ln_pre_kernel(
    const float* __restrict__ input_, const float* __restrict__ prev,
    const float* __restrict__ pos,
    const float* __restrict__ w1, const float* __restrict__ b1,
    const float* __restrict__ w2, const float* __restrict__ b2)
{
    __shared__ float sm[32];
    int r = blockIdx.x;
    int c = threadIdx.x;
    int n = r & (Nn - 1);
    size_t o = (size_t)r * Cc + c;

    float x = input_[o] + pos[(size_t)n * Cc + c];
    g_xpos[o] = x;
    float2 ss = block_sum2(x, x * x, sm);
    float mu = ss.x * (1.f / Cc);
    float var = ss.y * (1.f / Cc) - mu * mu;
    g_xln[o] = (x - mu) * rsqrtf(var + 1e-5f) * w1[c] + b1[c];

    float s = prev[o];
    ss = block_sum2(s, s * s, sm);
    mu = ss.x * (1.f / Cc);
    var = ss.y * (1.f / Cc) - mu * mu;
    g_sln[o] = (s - mu) * rsqrtf(var + 1e-5f) * w2[c] + b2[c];
}

// ---------------- generic tiled SGEMM: C = sum_p A_p @ W_p^T (+bias,act) ----
// A: [M,K] row-major. W: [Nt, ldw] row-major (torch Linear weight layout).
// act: 0 none, 1 exact gelu, 2 sigmoid. resid: C += v instead of C = v.
#define BM 128
#define BN 128
#define BKK 16
#define TM 8
#define TN 8

__global__ void __launch_bounds__(256, 2) sgemm_kernel(
    const float* __restrict__ A0, const float* __restrict__ A1,
    const float* __restrict__ W0, const float* __restrict__ W1,
    const float* __restrict__ bias, float* __restrict__ Cmat,
    int M, int Nt, int K, int ldw, int act, int resid)
{
    __shared__ float As[BKK][BM + 4];
    __shared__ float Bs[BKK][BN + 4];
    const int t = threadIdx.x;
    const int bm = blockIdx.y * BM;
    const int bn = blockIdx.x * BN;
    const int tr = (t >> 4) * TM;
    const int tc = (t & 15) * TN;

    float acc[TM][TN];
    #pragma unroll
    for (int i = 0; i < TM; i++)
        #pragma unroll
        for (int j = 0; j < TN; j++) acc[i][j] = 0.f;

    const int npairs = (A1 != nullptr) ? 2 : 1;
    for (int p = 0; p < npairs; p++) {
        const float* __restrict__ A = p ? A1 : A0;
        const float* __restrict__ W = p ? W1 : W0;
        for (int k0 = 0; k0 < K; k0 += BKK) {
            #pragma unroll
            for (int i = 0; i < 2; i++) {
                int f = t + i * 256;
                int row = f >> 2, kq = f & 3;
                float4 v = *reinterpret_cast<const float4*>(
                    &A[(size_t)(bm + row) * K + k0 + kq * 4]);
                As[kq * 4 + 0][row] = v.x;
                As[kq * 4 + 1][row] = v.y;
                As[kq * 4 + 2][row] = v.z;
                As[kq * 4 + 3][row] = v.w;
            }
            #pragma unroll
            for (int i = 0; i < 2; i++) {
                int f = t + i * 256;
                int row = f >> 2, kq = f & 3;
                float4 v = *reinterpret_cast<const float4*>(
                    &W[(size_t)(bn + row) * ldw + k0 + kq * 4]);
                Bs[kq * 4 + 0][row] = v.x;
                Bs[kq * 4 + 1][row] = v.y;
                Bs[kq * 4 + 2][row] = v.z;
                Bs[kq * 4 + 3][row] = v.w;
            }
            __syncthreads();
            #pragma unroll
            for (int kk = 0; kk < BKK; kk++) {
                float4 a0 = *reinterpret_cast<const float4*>(&As[kk][tr]);
                float4 a1 = *reinterpret_cast<const float4*>(&As[kk][tr + 4]);
                float4 b0 = *reinterpret_cast<const float4*>(&Bs[kk][tc]);
                float4 b1 = *reinterpret_cast<const float4*>(&Bs[kk][tc + 4]);
                float av[TM] = {a0.x, a0.y, a0.z, a0.w, a1.x, a1.y, a1.z, a1.w};
                float bv[TN] = {b0.x, b0.y, b0.z, b0.w, b1.x, b1.y, b1.z, b1.w};
                #pragma unroll
                for (int i = 0; i < TM; i++)
                    #pragma unroll
                    for (int j = 0; j < TN; j++)
                        acc[i][j] = fmaf(av[i], bv[j], acc[i][j]);
            }
            __syncthreads();
        }
    }

    #pragma unroll
    for (int i = 0; i < TM; i++) {
        int r = bm + tr + i;
        #pragma unroll
        for (int j = 0; j < TN; j++) {
            int c = bn + tc + j;
            float v = acc[i][j];
            if (bias) v += bias[c];
            if (act == 1) v = 0.5f * v * (1.f + erff(v * 0.70710678118654752f));
            else if (act == 2) v = 1.f / (1.f + expf(-v));
            size_t o = (size_t)r * Nt + c;
            if (resid) Cmat[o] += v;
            else       Cmat[o] = v;
        }
    }
}

// ---------------- kv = sum_n phi(k)[n,d] * v[n,e], split over N chunks ------
__global__ void zero_kv_kernel() {
    int i = blockIdx.x * 1024 + threadIdx.x;
    g_kv[i] = 0.f;
}

__global__ void __launch_bounds__(256) kv_kernel() {
    const int bh = blockIdx.x;      // 0..63
    const int chunk = blockIdx.y;   // 0..15 -> 256 rows each
    const int b = bh >> 3, h = bh & 7;
    __shared__ float ks[32][33];
    __shared__ float vs[32][33];
    const int t = threadIdx.x;
    const int d = t >> 3;
    const int e0 = (t & 7) * 4;
    float acc[4] = {0.f, 0.f, 0.f, 0.f};
    const int nbase = chunk * 256;

    for (int nb = 0; nb < 256; nb += 32) {
        #pragma unroll
        for (int i = 0; i < 4; i++) {
            int idx = t + i * 256;
            int row = idx >> 5, col = idx & 31;
            size_t base = ((size_t)(b * Nn + nbase + nb + row)) * (3 * Cc) + h * Dd + col;
            float kvl = g_qkv[base + Cc];
            ks[row][col] = phi_fn(kvl);
            vs[row][col] = g_qkv[base + 2 * Cc];
        }
        __syncthreads();
        #pragma unroll
        for (int nn = 0; nn < 32; nn++) {
            float kd = ks[nn][d];
            #pragma unroll
            for (int j = 0; j < 4; j++)
                acc[j] = fmaf(kd, vs[nn][e0 + j], acc[j]);
        }
        __syncthreads();
    }
    #pragma unroll
    for (int j = 0; j < 4; j++)
        atomicAdd(&g_kv[(size_t)bh * (Dd * Dd) + d * Dd + e0 + j], acc[j]);
}

// ---------------- attn_pre[b,n,h*D+e] = sum_d phi(q)[d] * kv[b,h,d,e] -------
__global__ void __launch_bounds__(256) attn_kernel() {
    const int r = blockIdx.x;
    const int b = r >> 12; // / 4096
    const int c = threadIdx.x;
    __shared__ float pq[Cc];
    float q = g_qkv[(size_t)r * (3 * Cc) + c];
    pq[c] = phi_fn(q);
    __syncthreads();
    const int h = c >> 5, e = c & 31;
    const float* kvp = &g_kv[((size_t)(b * Hh + h)) * (Dd * Dd) + e];
    const float* pqh = &pq[h * Dd];
    float s = 0.f;
    #pragma unroll
    for (int d2 = 0; d2 < Dd; d2++)
        s = fmaf(pqh[d2], kvp[d2 * Dd], s);
    g_attnpre[(size_t)r * Cc + c] = s;
}

// ------- fused: output_mid, new_state (gate), LN3(output_mid) ---------------
__global__ void __launch_bounds__(256) fuse_mid_kernel(
    const float* __restrict__ prev,
    const float* __restrict__ w3, const float* __restrict__ b3,
    float* __restrict__ out, float* __restrict__ nstate)
{
    __shared__ float sm[32];
    int r = blockIdx.x;
    int c = threadIdx.x;
    size_t o = (size_t)r * Cc + c;
    float a = g_attnproj[o];
    float om = g_xpos[o] + a;
    out[o] = om;
    float u = g_update[o];
    nstate[o] = prev[o] * (1.f - u) + a * u;
    float2 ss = block_sum2(om, om * om, sm);
    float mu = ss.x * (1.f / Cc);
    float var = ss.y * (1.f / Cc) - mu * mu;
    g_hln[o] = (om - mu) * rsqrtf(var + 1e-5f) * w3[c] + b3[c];
}

// ---------------- launch ----------------------------------------------------
extern "C" void kernel_launch(void* const* d_in, const int* in_sizes, int n_in,
                              void* d_out, int out_size) {
    const float* input_   = (const float*)d_in[0];
    const float* prev     = (const float*)d_in[1];
    const float* pos      = (const float*)d_in[2];
    const float* n1w      = (const float*)d_in[3];
    const float* n1b      = (const float*)d_in[4];
    const float* n2w      = (const float*)d_in[5];
    const float* n2b      = (const float*)d_in[6];
    const float* n3w      = (const float*)d_in[7];
    const float* n3b      = (const float*)d_in[8];
    const float* qkv_iw   = (const float*)d_in[9];
    const float* qkv_sw   = (const float*)d_in[10];
    const float* proj_w   = (const float*)d_in[11];
    const float* proj_b   = (const float*)d_in[12];
    const float* gate_w   = (const float*)d_in[13];
    const float* gate_b   = (const float*)d_in[14];
    const float* fc1_w    = (const float*)d_in[15];
    const float* fc1_b    = (const float*)d_in[16];
    const float* fc2_w    = (const float*)d_in[17];
    const float* fc2_b    = (const float*)d_in[18];

    float* out    = (float*)d_out;
    float* nstate = out + (size_t)out_size / 2;

    // Scratch pointers (non-enqueuing host queries; capture-safe)
    float *p_xln, *p_sln, *p_qkv, *p_attnpre, *p_attnproj, *p_update, *p_hln, *p_fc1;
    cudaGetSymbolAddress((void**)&p_xln, g_xln);
    cudaGetSymbolAddress((void**)&p_sln, g_sln);
    cudaGetSymbolAddress((void**)&p_qkv, g_qkv);
    cudaGetSymbolAddress((void**)&p_attnpre, g_attnpre);
    cudaGetSymbolAddress((void**)&p_attnproj, g_attnproj);
    cudaGetSymbolAddress((void**)&p_update, g_update);
    cudaGetSymbolAddress((void**)&p_hln, g_hln);
    cudaGetSymbolAddress((void**)&p_fc1, g_fc1);

    // 1) x_pos + LN1 + LN2
    ln_pre_kernel<<<Mrows, 256>>>(input_, prev, pos, n1w, n1b, n2w, n2b);

    // 2) qkv = x_ln @ Wi^T + s_ln @ Ws^T   [M, 768]
    sgemm_kernel<<<dim3(768 / BN, Mrows / BM), 256>>>(
        p_xln, p_sln, qkv_iw, qkv_sw, nullptr, p_qkv,
        Mrows, 3 * Cc, Cc, Cc, 0, 0);

    // 3) kv[b,h,d,e]
    zero_kv_kernel<<<64, 1024>>>();
    kv_kernel<<<dim3(Bb * Hh, 16), 256>>>();

    // 4) attn_pre = phi_q @ kv
    attn_kernel<<<Mrows, 256>>>();

    // 5) proj: attn_proj = attn_pre @ proj_w^T + proj_b
    sgemm_kernel<<<dim3(Cc / BN, Mrows / BM), 256>>>(
        p_attnpre, nullptr, proj_w, nullptr, proj_b, p_attnproj,
        Mrows, Cc, Cc, Cc, 0, 0);

    // 6) gate: update = sigmoid([input_, prev] @ gate_w^T + gate_b)
    sgemm_kernel<<<dim3(Cc / BN, Mrows / BM), 256>>>(
        input_, prev, gate_w, gate_w + Cc, gate_b, p_update,
        Mrows, Cc, Cc, 2 * Cc, 2, 0);

    // 7) output_mid -> d_out, new_state -> d_out half2, LN3 -> g_hln
    fuse_mid_kernel<<<Mrows, 256>>>(prev, n3w, n3b, out, nstate);

    // 8) fc1 with exact-gelu epilogue
    sgemm_kernel<<<dim3(HID / BN, Mrows / BM), 256>>>(
        p_hln, nullptr, fc1_w, nullptr, fc1_b, p_fc1,
        Mrows, HID, Cc, Cc, 1, 0);

    // 9) fc2, accumulate into output residual
    sgemm_kernel<<<dim3(Cc / BN, Mrows / BM), 256>>>(
        p_fc1, nullptr, fc2_w, nullptr, fc2_b, out,
        Mrows, Cc, HID, HID, 0, 1);
}